// round 7
// baseline (speedup 1.0000x reference)
#include <cuda_runtime.h>

// ---------------------------------------------------------------------------
// LNon_16621523436082 — 3 kernels only:
//   k_minmax : per-block min/max of raw data; block0 zeroes g_hist  [DRAM read]
//   k_hist   : per-block prep (reduce g_bmin/g_bmax -> dmin/invw) +
//              5-bin histogram -> 5 global atomics                 [DRAM read]
//   k_main   : per-block stats (counts -> accum/frame/tables) +
//              elementwise transform, __stcs stores                [read+write]
// All big loops 4-wide batched (4 independent float4 loads in flight per
// thread) to raise MLP; grid-stride keeps coalescing.
// ---------------------------------------------------------------------------

#define NBLK 2048
#define TPB  256
#define SATF 16777216.0f
#define FLTMAX 3.4028235e38f

__device__ float    g_bmin[NBLK];
__device__ float    g_bmax[NBLK];
__device__ unsigned g_hist[8];

// ---- pass 1: per-block min/max of raw data -------------------------------
__global__ void __launch_bounds__(TPB) k_minmax(const float4* __restrict__ d4, int n4, int n) {
    if (blockIdx.x == 0 && threadIdx.x < 8) g_hist[threadIdx.x] = 0u;  // replay-safe reset

    float mn = FLTMAX, mx = -FLTMAX;
    const int stride = gridDim.x * blockDim.x;
    const int gtid = blockIdx.x * blockDim.x + threadIdx.x;

    int i = gtid;
    for (; i + 3 * stride < n4; i += 4 * stride) {
        float4 a = d4[i];
        float4 b = d4[i + stride];
        float4 c = d4[i + 2 * stride];
        float4 e = d4[i + 3 * stride];
        mn = fminf(mn, fminf(fminf(a.x, a.y), fminf(a.z, a.w)));
        mx = fmaxf(mx, fmaxf(fmaxf(a.x, a.y), fmaxf(a.z, a.w)));
        mn = fminf(mn, fminf(fminf(b.x, b.y), fminf(b.z, b.w)));
        mx = fmaxf(mx, fmaxf(fmaxf(b.x, b.y), fmaxf(b.z, b.w)));
        mn = fminf(mn, fminf(fminf(c.x, c.y), fminf(c.z, c.w)));
        mx = fmaxf(mx, fmaxf(fmaxf(c.x, c.y), fmaxf(c.z, c.w)));
        mn = fminf(mn, fminf(fminf(e.x, e.y), fminf(e.z, e.w)));
        mx = fmaxf(mx, fmaxf(fmaxf(e.x, e.y), fmaxf(e.z, e.w)));
    }
    for (; i < n4; i += stride) {
        float4 v = d4[i];
        mn = fminf(mn, fminf(fminf(v.x, v.y), fminf(v.z, v.w)));
        mx = fmaxf(mx, fmaxf(fmaxf(v.x, v.y), fmaxf(v.z, v.w)));
    }
    int base = n4 * 4;
    if (gtid < n - base) {
        float v = ((const float*)d4)[base + gtid];
        mn = fminf(mn, v); mx = fmaxf(mx, v);
    }
    #pragma unroll
    for (int o = 16; o; o >>= 1) {
        mn = fminf(mn, __shfl_xor_sync(0xffffffffu, mn, o));
        mx = fmaxf(mx, __shfl_xor_sync(0xffffffffu, mx, o));
    }
    __shared__ float smn[8], smx[8];
    int w = threadIdx.x >> 5;
    if ((threadIdx.x & 31) == 0) { smn[w] = mn; smx[w] = mx; }
    __syncthreads();
    if (threadIdx.x < 8) {
        mn = smn[threadIdx.x]; mx = smx[threadIdx.x];
        #pragma unroll
        for (int o = 4; o; o >>= 1) {
            mn = fminf(mn, __shfl_xor_sync(0xffu, mn, o));
            mx = fmaxf(mx, __shfl_xor_sync(0xffu, mx, o));
        }
        if (threadIdx.x == 0) { g_bmin[blockIdx.x] = mn; g_bmax[blockIdx.x] = mx; }
    }
}

// ---- pass 2: per-block prep + 5-bin histogram ----------------------------
__global__ void __launch_bounds__(TPB) k_hist(const float4* __restrict__ d4,
                                              const float* __restrict__ ctp,
                                              int n4, int n) {
    // --- per-block redundant prep: reduce per-block min/max arrays --------
    __shared__ float s_dmin, s_invw;
    {
        float mn = FLTMAX, mx = -FLTMAX;
        for (int i = threadIdx.x; i < NBLK; i += TPB) {
            mn = fminf(mn, g_bmin[i]);
            mx = fmaxf(mx, g_bmax[i]);
        }
        #pragma unroll
        for (int o = 16; o; o >>= 1) {
            mn = fminf(mn, __shfl_xor_sync(0xffffffffu, mn, o));
            mx = fmaxf(mx, __shfl_xor_sync(0xffffffffu, mx, o));
        }
        __shared__ float smn[8], smx[8];
        int w = threadIdx.x >> 5;
        if ((threadIdx.x & 31) == 0) { smn[w] = mn; smx[w] = mx; }
        __syncthreads();
        if (threadIdx.x == 0) {
            #pragma unroll
            for (int k = 1; k < 8; k++) { mn = fminf(mn, smn[k]); mx = fmaxf(mx, smx[k]); }
            float ct = *ctp;
            float a = ct * mn, b = ct * mx;
            float lo = fminf(a, b), hi = fmaxf(a, b);
            float dmin  = lo - 0.1f;
            float dmax  = hi + 0.1f;
            float width = (dmax - dmin) / 5.0f;
            s_dmin = dmin;
            s_invw = 1.0f / width;
        }
        __syncthreads();
    }
    const float ct   = __ldg(ctp);
    const float dmin = s_dmin, invw = s_invw;

    unsigned c0 = 0, c1 = 0, c2 = 0, c3 = 0, c4 = 0;
    auto acc = [&](float x) {
        float v = x * ct;
        int b = (int)floorf((v - dmin) * invw);
        b = min(max(b, 0), 4);
        c0 += (b == 0); c1 += (b == 1); c2 += (b == 2); c3 += (b == 3); c4 += (b == 4);
    };

    const int stride = gridDim.x * blockDim.x;
    const int gtid = blockIdx.x * blockDim.x + threadIdx.x;
    int i = gtid;
    for (; i + 3 * stride < n4; i += 4 * stride) {
        float4 a = d4[i];
        float4 b = d4[i + stride];
        float4 c = d4[i + 2 * stride];
        float4 e = d4[i + 3 * stride];
        acc(a.x); acc(a.y); acc(a.z); acc(a.w);
        acc(b.x); acc(b.y); acc(b.z); acc(b.w);
        acc(c.x); acc(c.y); acc(c.z); acc(c.w);
        acc(e.x); acc(e.y); acc(e.z); acc(e.w);
    }
    for (; i < n4; i += stride) {
        float4 v = d4[i];
        acc(v.x); acc(v.y); acc(v.z); acc(v.w);
    }
    int base = n4 * 4;
    if (gtid < n - base) acc(((const float*)d4)[base + gtid]);

    __shared__ unsigned s[5];
    if (threadIdx.x < 5) s[threadIdx.x] = 0;
    __syncthreads();
    atomicAdd(&s[0], c0); atomicAdd(&s[1], c1); atomicAdd(&s[2], c2);
    atomicAdd(&s[3], c3); atomicAdd(&s[4], c4);
    __syncthreads();
    if (threadIdx.x < 5) atomicAdd(&g_hist[threadIdx.x], s[threadIdx.x]);
}

// ---- pass 3: per-block stats + elementwise transform ---------------------
__global__ void __launch_bounds__(TPB) k_main(const float4* __restrict__ d4,
                                              const float* __restrict__ ctp,
                                              const float* __restrict__ stp,
                                              const float* __restrict__ params,
                                              float4* __restrict__ out,
                                              int n4, int n) {
    __shared__ float sg[5], sa[5], ssl[4], sA[5], sV[5];
    __shared__ float s_dmin, s_width;

    // re-derive dmin/width from the per-block arrays (same values as k_hist)
    {
        float mn = FLTMAX, mx = -FLTMAX;
        for (int i = threadIdx.x; i < NBLK; i += TPB) {
            mn = fminf(mn, g_bmin[i]);
            mx = fmaxf(mx, g_bmax[i]);
        }
        #pragma unroll
        for (int o = 16; o; o >>= 1) {
            mn = fminf(mn, __shfl_xor_sync(0xffffffffu, mn, o));
            mx = fmaxf(mx, __shfl_xor_sync(0xffffffffu, mx, o));
        }
        __shared__ float smn[8], smx[8];
        int w = threadIdx.x >> 5;
        if ((threadIdx.x & 31) == 0) { smn[w] = mn; smx[w] = mx; }
        __syncthreads();
        if (threadIdx.x == 0) {
            #pragma unroll
            for (int k = 1; k < 8; k++) { mn = fminf(mn, smn[k]); mx = fmaxf(mx, smx[k]); }
            float ct = *ctp;
            float a = ct * mn, b = ct * mx;
            float lo = fminf(a, b), hi = fmaxf(a, b);
            s_dmin  = lo - 0.1f;
            s_width = ((hi + 0.1f) - (lo - 0.1f)) / 5.0f;
        }
        __syncthreads();
    }

    // per-block redundant stats from the 5 histogram words
    if (threadIdx.x == 0) {
        float counts[5];
        #pragma unroll
        for (int j = 0; j < 5; j++) counts[j] = fminf((float)g_hist[j], SATF);  // fp32 scatter-add saturation
        float sum = counts[0] + counts[1] + counts[2] + counts[3] + counts[4];
        float accum[5];
        float a = 0.0f;
        #pragma unroll
        for (int j = 0; j < 5; j++) { a += counts[j] / sum; accum[j] = a * 5.0f; }
        float dmin = s_dmin, width = s_width;
        float grid[5];
        #pragma unroll
        for (int i2 = 0; i2 < 5; i2++) {
            float e0 = dmin + width * (float)i2;
            float e1 = dmin + width * (float)(i2 + 1);
            grid[i2] = 0.5f * (e0 + e1);
        }
        #pragma unroll
        for (int j = 0; j < 4; j++) {
            float den = grid[j + 1] - grid[j];
            if (den == 0.0f) den = 1.0f;
            ssl[j] = (accum[j + 1] - accum[j]) / den;
        }
        float frame[5];
        #pragma unroll
        for (int i2 = 0; i2 < 5; i2++) {
            float xq = (float)i2;
            int pos = 0;
            #pragma unroll
            for (int k = 0; k < 5; k++) pos += (accum[k] < xq);
            int idx = min(max(pos - 1, 0), 3);
            float den = accum[idx + 1] - accum[idx];
            if (den == 0.0f) den = 1.0f;
            frame[i2] = grid[idx] + (grid[idx + 1] - grid[idx]) / den * (xq - accum[idx]);
        }
        #pragma unroll
        for (int i2 = 0; i2 < 5; i2++) {
            sg[i2] = grid[i2];
            sa[i2] = accum[i2];
            sA[i2] = frame[i2] + 0.001f * params[i2];       // theta row
            sV[i2] = frame[i2] + 0.001f * params[5 + i2];   // velocity row
        }
    }
    __syncthreads();

    const float ct = __ldg(ctp), st = __ldg(stp);

    auto f = [&](float x) -> float {
        float v = x * ct;
        int pos = (v > sg[0]) + (v > sg[1]) + (v > sg[2]) + (v > sg[3]) + (v > sg[4]);
        int idx = min(max(pos - 1, 0), 3);
        float index = sa[idx] + ssl[idx] * (v - sg[idx]);
        float bf = floorf(index);
        float p = index - bf;
        int bi = (int)bf;
        int b = min(max(bi, 0), 4);
        int e = min(max(bi + 1, 0), 4);
        float th = (1.0f - p) * sA[b] + p * sA[e];
        float vl = (1.0f - p) * sV[b] + p * sV[e];
        float s, co;
        __sincosf(th, &s, &co);
        return (v * (1.0f + vl * s) + vl * co) * st;
    };

    const int stride = gridDim.x * blockDim.x;
    const int gtid = blockIdx.x * blockDim.x + threadIdx.x;
    int i = gtid;
    for (; i + 3 * stride < n4; i += 4 * stride) {
        float4 a = d4[i];
        float4 b = d4[i + stride];
        float4 c = d4[i + 2 * stride];
        float4 e = d4[i + 3 * stride];
        float4 oa, ob, oc, oe;
        oa.x = f(a.x); oa.y = f(a.y); oa.z = f(a.z); oa.w = f(a.w);
        ob.x = f(b.x); ob.y = f(b.y); ob.z = f(b.z); ob.w = f(b.w);
        oc.x = f(c.x); oc.y = f(c.y); oc.z = f(c.z); oc.w = f(c.w);
        oe.x = f(e.x); oe.y = f(e.y); oe.z = f(e.z); oe.w = f(e.w);
        __stcs(&out[i], oa);
        __stcs(&out[i + stride], ob);
        __stcs(&out[i + 2 * stride], oc);
        __stcs(&out[i + 3 * stride], oe);
    }
    for (; i < n4; i += stride) {
        float4 v = d4[i];
        float4 o;
        o.x = f(v.x); o.y = f(v.y); o.z = f(v.z); o.w = f(v.w);
        __stcs(&out[i], o);
    }
    int base = n4 * 4;
    if (gtid < n - base) {
        float r = f(((const float*)d4)[base + gtid]);
        __stcs(&((float*)out)[base + gtid], r);
    }
}

extern "C" void kernel_launch(void* const* d_in, const int* in_sizes, int n_in,
                              void* d_out, int out_size) {
    const float* data   = (const float*)d_in[0];
    const float* params = (const float*)d_in[1];
    const float* ctp    = (const float*)d_in[2];
    const float* stp    = (const float*)d_in[3];
    float* out = (float*)d_out;
    int n  = in_sizes[0];
    int n4 = n / 4;

    k_minmax<<<NBLK, TPB>>>((const float4*)data, n4, n);
    k_hist<<<NBLK, TPB>>>((const float4*)data, ctp, n4, n);
    k_main<<<NBLK, TPB>>>((const float4*)data, ctp, stp, params, (float4*)out, n4, n);
}

// round 8
// speedup vs baseline: 1.1333x; 1.1333x over previous
#include <cuda_runtime.h>

// ---------------------------------------------------------------------------
// LNon_16621523436082 — 3 kernels:
//   k_minmax : per-block min/max (at HBM read ceiling, 73% spec)   [23.5us]
//   k_hist   : per-block prep + 5-bin histogram (memory bound)     [~24us]
//   k_main   : SLIMMED transform: equally-spaced-grid segment find,
//              precomputed line coeffs (float2 tables), clamped-index
//              delta-table gather, st folded into velocity tables.
//              ~21 warp-instr / 32 elems -> memory bound.          [~50us]
// ---------------------------------------------------------------------------

#define NBLK 2048
#define TPB  256
#define SATF 16777216.0f
#define FLTMAX 3.4028235e38f

__device__ float    g_bmin[NBLK];
__device__ float    g_bmax[NBLK];
__device__ unsigned g_hist[8];

// ---- pass 1: per-block min/max of raw data -------------------------------
__global__ void __launch_bounds__(TPB) k_minmax(const float4* __restrict__ d4, int n4, int n) {
    if (blockIdx.x == 0 && threadIdx.x < 8) g_hist[threadIdx.x] = 0u;  // replay-safe reset

    float mn = FLTMAX, mx = -FLTMAX;
    const int stride = gridDim.x * blockDim.x;
    const int gtid = blockIdx.x * blockDim.x + threadIdx.x;

    int i = gtid;
    for (; i + 3 * stride < n4; i += 4 * stride) {
        float4 a = d4[i];
        float4 b = d4[i + stride];
        float4 c = d4[i + 2 * stride];
        float4 e = d4[i + 3 * stride];
        mn = fminf(mn, fminf(fminf(a.x, a.y), fminf(a.z, a.w)));
        mx = fmaxf(mx, fmaxf(fmaxf(a.x, a.y), fmaxf(a.z, a.w)));
        mn = fminf(mn, fminf(fminf(b.x, b.y), fminf(b.z, b.w)));
        mx = fmaxf(mx, fmaxf(fmaxf(b.x, b.y), fmaxf(b.z, b.w)));
        mn = fminf(mn, fminf(fminf(c.x, c.y), fminf(c.z, c.w)));
        mx = fmaxf(mx, fmaxf(fmaxf(c.x, c.y), fmaxf(c.z, c.w)));
        mn = fminf(mn, fminf(fminf(e.x, e.y), fminf(e.z, e.w)));
        mx = fmaxf(mx, fmaxf(fmaxf(e.x, e.y), fmaxf(e.z, e.w)));
    }
    for (; i < n4; i += stride) {
        float4 v = d4[i];
        mn = fminf(mn, fminf(fminf(v.x, v.y), fminf(v.z, v.w)));
        mx = fmaxf(mx, fmaxf(fmaxf(v.x, v.y), fmaxf(v.z, v.w)));
    }
    int base = n4 * 4;
    if (gtid < n - base) {
        float v = ((const float*)d4)[base + gtid];
        mn = fminf(mn, v); mx = fmaxf(mx, v);
    }
    #pragma unroll
    for (int o = 16; o; o >>= 1) {
        mn = fminf(mn, __shfl_xor_sync(0xffffffffu, mn, o));
        mx = fmaxf(mx, __shfl_xor_sync(0xffffffffu, mx, o));
    }
    __shared__ float smn[8], smx[8];
    int w = threadIdx.x >> 5;
    if ((threadIdx.x & 31) == 0) { smn[w] = mn; smx[w] = mx; }
    __syncthreads();
    if (threadIdx.x < 8) {
        mn = smn[threadIdx.x]; mx = smx[threadIdx.x];
        #pragma unroll
        for (int o = 4; o; o >>= 1) {
            mn = fminf(mn, __shfl_xor_sync(0xffu, mn, o));
            mx = fmaxf(mx, __shfl_xor_sync(0xffu, mx, o));
        }
        if (threadIdx.x == 0) { g_bmin[blockIdx.x] = mn; g_bmax[blockIdx.x] = mx; }
    }
}

// ---- pass 2: per-block prep + 5-bin histogram ----------------------------
__global__ void __launch_bounds__(TPB) k_hist(const float4* __restrict__ d4,
                                              const float* __restrict__ ctp,
                                              int n4, int n) {
    __shared__ float s_dmin, s_invw;
    {
        float mn = FLTMAX, mx = -FLTMAX;
        for (int i = threadIdx.x; i < NBLK; i += TPB) {
            mn = fminf(mn, g_bmin[i]);
            mx = fmaxf(mx, g_bmax[i]);
        }
        #pragma unroll
        for (int o = 16; o; o >>= 1) {
            mn = fminf(mn, __shfl_xor_sync(0xffffffffu, mn, o));
            mx = fmaxf(mx, __shfl_xor_sync(0xffffffffu, mx, o));
        }
        __shared__ float smn[8], smx[8];
        int w = threadIdx.x >> 5;
        if ((threadIdx.x & 31) == 0) { smn[w] = mn; smx[w] = mx; }
        __syncthreads();
        if (threadIdx.x == 0) {
            #pragma unroll
            for (int k = 1; k < 8; k++) { mn = fminf(mn, smn[k]); mx = fmaxf(mx, smx[k]); }
            float ct = *ctp;
            float a = ct * mn, b = ct * mx;
            float lo = fminf(a, b), hi = fmaxf(a, b);
            float dmin  = lo - 0.1f;
            float dmax  = hi + 0.1f;
            float width = (dmax - dmin) / 5.0f;
            s_dmin = dmin;
            s_invw = 1.0f / width;
        }
        __syncthreads();
    }
    const float ct   = __ldg(ctp);
    const float dmin = s_dmin, invw = s_invw;

    unsigned c0 = 0, c1 = 0, c2 = 0, c3 = 0, c4 = 0;
    auto acc = [&](float x) {
        float v = x * ct;
        int b = (int)floorf((v - dmin) * invw);
        b = min(max(b, 0), 4);
        c0 += (b == 0); c1 += (b == 1); c2 += (b == 2); c3 += (b == 3); c4 += (b == 4);
    };

    const int stride = gridDim.x * blockDim.x;
    const int gtid = blockIdx.x * blockDim.x + threadIdx.x;
    int i = gtid;
    for (; i + 3 * stride < n4; i += 4 * stride) {
        float4 a = d4[i];
        float4 b = d4[i + stride];
        float4 c = d4[i + 2 * stride];
        float4 e = d4[i + 3 * stride];
        acc(a.x); acc(a.y); acc(a.z); acc(a.w);
        acc(b.x); acc(b.y); acc(b.z); acc(b.w);
        acc(c.x); acc(c.y); acc(c.z); acc(c.w);
        acc(e.x); acc(e.y); acc(e.z); acc(e.w);
    }
    for (; i < n4; i += stride) {
        float4 v = d4[i];
        acc(v.x); acc(v.y); acc(v.z); acc(v.w);
    }
    int base = n4 * 4;
    if (gtid < n - base) acc(((const float*)d4)[base + gtid]);

    __shared__ unsigned s[5];
    if (threadIdx.x < 5) s[threadIdx.x] = 0;
    __syncthreads();
    atomicAdd(&s[0], c0); atomicAdd(&s[1], c1); atomicAdd(&s[2], c2);
    atomicAdd(&s[3], c3); atomicAdd(&s[4], c4);
    __syncthreads();
    if (threadIdx.x < 5) atomicAdd(&g_hist[threadIdx.x], s[threadIdx.x]);
}

// ---- pass 3: slim elementwise transform ----------------------------------
__global__ void __launch_bounds__(TPB) k_main(const float4* __restrict__ d4,
                                              const float* __restrict__ ctp,
                                              const float* __restrict__ stp,
                                              const float* __restrict__ params,
                                              float4* __restrict__ out,
                                              int n4, int n) {
    // tables: sAB[j] = (A,B) with index = A + B*v on segment j (j=0..3)
    //         sTH[b] = (thBase, thDelta),  th = thBase + p*thDelta
    //         sVL[b] = (st*vlBase, st*vlDelta)  (st folded in)
    __shared__ float2 sAB[4], sTH[5], sVL[5];
    __shared__ float  s_g0, s_invw;

    // per-block redundant prep: min/max arrays -> dmin/width ---------------
    {
        float mn = FLTMAX, mx = -FLTMAX;
        for (int i = threadIdx.x; i < NBLK; i += TPB) {
            mn = fminf(mn, g_bmin[i]);
            mx = fmaxf(mx, g_bmax[i]);
        }
        #pragma unroll
        for (int o = 16; o; o >>= 1) {
            mn = fminf(mn, __shfl_xor_sync(0xffffffffu, mn, o));
            mx = fmaxf(mx, __shfl_xor_sync(0xffffffffu, mx, o));
        }
        __shared__ float smn[8], smx[8];
        int w = threadIdx.x >> 5;
        if ((threadIdx.x & 31) == 0) { smn[w] = mn; smx[w] = mx; }
        __syncthreads();

        if (threadIdx.x == 0) {
            #pragma unroll
            for (int k = 1; k < 8; k++) { mn = fminf(mn, smn[k]); mx = fmaxf(mx, smx[k]); }
            float ct = *ctp;
            float st = *stp;
            float a = ct * mn, b = ct * mx;
            float lo = fminf(a, b), hi = fmaxf(a, b);
            float dmin  = lo - 0.1f;
            float width = ((hi + 0.1f) - dmin) / 5.0f;

            // stats from the 5 histogram words (fp32 scatter-add saturation)
            float counts[5];
            #pragma unroll
            for (int j = 0; j < 5; j++) counts[j] = fminf((float)g_hist[j], SATF);
            float sum = counts[0] + counts[1] + counts[2] + counts[3] + counts[4];
            float accum[5];
            float acn = 0.0f;
            #pragma unroll
            for (int j = 0; j < 5; j++) { acn += counts[j] / sum; accum[j] = acn * 5.0f; }
            float grid[5];
            #pragma unroll
            for (int i2 = 0; i2 < 5; i2++) {
                float e0 = dmin + width * (float)i2;
                float e1 = dmin + width * (float)(i2 + 1);
                grid[i2] = 0.5f * (e0 + e1);
            }
            #pragma unroll
            for (int j = 0; j < 4; j++) {
                float den = grid[j + 1] - grid[j];
                if (den == 0.0f) den = 1.0f;
                float slope = (accum[j + 1] - accum[j]) / den;
                // index = accum[j] + slope*(v - grid[j]) = A + B*v
                sAB[j] = make_float2(accum[j] - slope * grid[j], slope);
            }
            float frame[5];
            #pragma unroll
            for (int i2 = 0; i2 < 5; i2++) {
                float xq = (float)i2;
                int pos = 0;
                #pragma unroll
                for (int k = 0; k < 5; k++) pos += (accum[k] < xq);
                int idx = min(max(pos - 1, 0), 3);
                float den = accum[idx + 1] - accum[idx];
                if (den == 0.0f) den = 1.0f;
                frame[i2] = grid[idx] + (grid[idx + 1] - grid[idx]) / den * (xq - accum[idx]);
            }
            float tA[5], tV[5];
            #pragma unroll
            for (int i2 = 0; i2 < 5; i2++) {
                tA[i2] = frame[i2] + 0.001f * params[i2];
                tV[i2] = frame[i2] + 0.001f * params[5 + i2];
            }
            #pragma unroll
            for (int b2 = 0; b2 < 5; b2++) {
                int e2 = min(b2 + 1, 4);
                sTH[b2] = make_float2(tA[b2], tA[e2] - tA[b2]);           // delta[4]=0
                sVL[b2] = make_float2(st * tV[b2], st * (tV[e2] - tV[b2]));
            }
            s_g0   = grid[0];
            s_invw = 1.0f / width;
        }
        __syncthreads();
    }

    const float ct = __ldg(ctp), st = __ldg(stp);
    const float g0 = s_g0, invw = s_invw;

    auto f = [&](float x) -> float {
        float v  = x * ct;
        // equally-spaced grid -> segment by one fma+cvt
        float fi = (v - g0) * invw;
        int idx  = min(max(__float2int_rd(fi), 0), 3);
        float2 ab = sAB[idx];
        float index = fmaf(ab.y, v, ab.x);
        // clamp index to [0,4]: matches reference b/e clip semantics exactly
        float ic = fminf(fmaxf(index, 0.0f), 4.0f);
        float bf = floorf(ic);
        float p  = ic - bf;
        int b    = (int)bf;               // 0..4 guaranteed
        float2 th2 = sTH[b];
        float2 vl2 = sVL[b];
        float th = fmaf(p, th2.y, th2.x);
        float q  = fmaf(p, vl2.y, vl2.x); // = st*velo
        float s, c;
        __sincosf(th, &s, &c);
        // out = st*v + q*(v*s + c)
        return fmaf(fmaf(v, s, c), q, v * st);
    };

    const int stride = gridDim.x * blockDim.x;
    const int gtid = blockIdx.x * blockDim.x + threadIdx.x;
    int i = gtid;
    for (; i + 3 * stride < n4; i += 4 * stride) {
        float4 a = d4[i];
        float4 b = d4[i + stride];
        float4 c = d4[i + 2 * stride];
        float4 e = d4[i + 3 * stride];
        float4 oa, ob, oc, oe;
        oa.x = f(a.x); oa.y = f(a.y); oa.z = f(a.z); oa.w = f(a.w);
        ob.x = f(b.x); ob.y = f(b.y); ob.z = f(b.z); ob.w = f(b.w);
        oc.x = f(c.x); oc.y = f(c.y); oc.z = f(c.z); oc.w = f(c.w);
        oe.x = f(e.x); oe.y = f(e.y); oe.z = f(e.z); oe.w = f(e.w);
        __stcs(&out[i], oa);
        __stcs(&out[i + stride], ob);
        __stcs(&out[i + 2 * stride], oc);
        __stcs(&out[i + 3 * stride], oe);
    }
    for (; i < n4; i += stride) {
        float4 v = d4[i];
        float4 o;
        o.x = f(v.x); o.y = f(v.y); o.z = f(v.z); o.w = f(v.w);
        __stcs(&out[i], o);
    }
    int base = n4 * 4;
    if (gtid < n - base) {
        float r = f(((const float*)d4)[base + gtid]);
        __stcs(&((float*)out)[base + gtid], r);
    }
}

extern "C" void kernel_launch(void* const* d_in, const int* in_sizes, int n_in,
                              void* d_out, int out_size) {
    const float* data   = (const float*)d_in[0];
    const float* params = (const float*)d_in[1];
    const float* ctp    = (const float*)d_in[2];
    const float* stp    = (const float*)d_in[3];
    float* out = (float*)d_out;
    int n  = in_sizes[0];
    int n4 = n / 4;

    k_minmax<<<NBLK, TPB>>>((const float4*)data, n4, n);
    k_hist<<<NBLK, TPB>>>((const float4*)data, ctp, n4, n);
    k_main<<<NBLK, TPB>>>((const float4*)data, ctp, stp, params, (float4*)out, n4, n);
}

// round 10
// speedup vs baseline: 1.1930x; 1.0526x over previous
#include <cuda_runtime.h>

// ---------------------------------------------------------------------------
// LNon_16621523436082 — 3 kernels, contiguous per-block slices with
// alternating traversal direction for cross-launch L2 reuse (L2 ~120MB
// persists across launches; only L1 is flushed):
//   k_minmax : slice FORWARD  (pure DRAM read; leaves slice-ends hot)
//   k_hist   : slice BACKWARD (starts on hot ends -> mostly L2)
//   k_main   : slice FORWARD  (starts on hot starts), __stcs writes
// ---------------------------------------------------------------------------

#define NBLK 2048
#define TPB  256
#define SATF 16777216.0f
#define FLTMAX 3.4028235e38f

__device__ float    g_bmin[NBLK];
__device__ float    g_bmax[NBLK];
__device__ unsigned g_hist[8];

__device__ __forceinline__ void slice_bounds(int n4, int& start, int& len) {
    int base = n4 / NBLK, rem = n4 % NBLK;
    start = blockIdx.x * base + min((int)blockIdx.x, rem);
    len   = base + (blockIdx.x < rem ? 1 : 0);
}

// ---- pass 1: per-block min/max, slice forward ----------------------------
__global__ void __launch_bounds__(TPB) k_minmax(const float4* __restrict__ d4, int n4, int n) {
    if (blockIdx.x == 0 && threadIdx.x < 8) g_hist[threadIdx.x] = 0u;  // replay-safe reset

    int start, len;
    slice_bounds(n4, start, len);

    float mn = FLTMAX, mx = -FLTMAX;
    auto red = [&](float4 v) {
        mn = fminf(mn, fminf(fminf(v.x, v.y), fminf(v.z, v.w)));
        mx = fmaxf(mx, fmaxf(fmaxf(v.x, v.y), fmaxf(v.z, v.w)));
    };

    int j = threadIdx.x;
    for (; j + 3 * TPB < len; j += 4 * TPB) {
        float4 a = d4[start + j];
        float4 b = d4[start + j + TPB];
        float4 c = d4[start + j + 2 * TPB];
        float4 e = d4[start + j + 3 * TPB];
        red(a); red(b); red(c); red(e);
    }
    for (; j < len; j += TPB) red(d4[start + j]);

    int base = n4 * 4;
    int gtid = blockIdx.x * TPB + threadIdx.x;
    if (gtid < n - base) {
        float v = ((const float*)d4)[base + gtid];
        mn = fminf(mn, v); mx = fmaxf(mx, v);
    }
    #pragma unroll
    for (int o = 16; o; o >>= 1) {
        mn = fminf(mn, __shfl_xor_sync(0xffffffffu, mn, o));
        mx = fmaxf(mx, __shfl_xor_sync(0xffffffffu, mx, o));
    }
    __shared__ float smn[8], smx[8];
    int w = threadIdx.x >> 5;
    if ((threadIdx.x & 31) == 0) { smn[w] = mn; smx[w] = mx; }
    __syncthreads();
    if (threadIdx.x < 8) {
        mn = smn[threadIdx.x]; mx = smx[threadIdx.x];
        #pragma unroll
        for (int o = 4; o; o >>= 1) {
            mn = fminf(mn, __shfl_xor_sync(0xffu, mn, o));
            mx = fmaxf(mx, __shfl_xor_sync(0xffu, mx, o));
        }
        if (threadIdx.x == 0) { g_bmin[blockIdx.x] = mn; g_bmax[blockIdx.x] = mx; }
    }
}

// ---- pass 2: per-block prep + 5-bin histogram, slice backward ------------
__global__ void __launch_bounds__(TPB) k_hist(const float4* __restrict__ d4,
                                              const float* __restrict__ ctp,
                                              int n4, int n) {
    __shared__ float s_scale, s_bias;   // bin = floor(x*scale + bias)
    {
        float mn = FLTMAX, mx = -FLTMAX;
        for (int i = threadIdx.x; i < NBLK; i += TPB) {
            mn = fminf(mn, g_bmin[i]);
            mx = fmaxf(mx, g_bmax[i]);
        }
        #pragma unroll
        for (int o = 16; o; o >>= 1) {
            mn = fminf(mn, __shfl_xor_sync(0xffffffffu, mn, o));
            mx = fmaxf(mx, __shfl_xor_sync(0xffffffffu, mx, o));
        }
        __shared__ float smn[8], smx[8];
        int w = threadIdx.x >> 5;
        if ((threadIdx.x & 31) == 0) { smn[w] = mn; smx[w] = mx; }
        __syncthreads();
        if (threadIdx.x == 0) {
            #pragma unroll
            for (int k = 1; k < 8; k++) { mn = fminf(mn, smn[k]); mx = fmaxf(mx, smx[k]); }
            float ct = *ctp;
            float a = ct * mn, b = ct * mx;
            float lo = fminf(a, b), hi = fmaxf(a, b);
            float dmin  = lo - 0.1f;
            float width = ((hi + 0.1f) - dmin) / 5.0f;
            float invw  = 1.0f / width;
            s_scale = ct * invw;        // (x*ct - dmin)*invw = x*scale + bias
            s_bias  = -dmin * invw;
        }
        __syncthreads();
    }
    const float scale = s_scale, bias = s_bias;

    // packed counters: 5 fields x 12 bits (per-thread <= ~70 elems, fits)
    unsigned long long acc = 0ull;
    auto cnt = [&](float x) {
        int b = __float2int_rd(fmaf(x, scale, bias));
        b = min(max(b, 0), 4);
        acc += 1ull << (b * 12);
    };

    int start, len;
    slice_bounds(n4, start, len);
    int last = start + len - 1;

    int j = threadIdx.x;
    for (; j + 3 * TPB < len; j += 4 * TPB) {
        float4 a = d4[last - j];
        float4 b = d4[last - j - TPB];
        float4 c = d4[last - j - 2 * TPB];
        float4 e = d4[last - j - 3 * TPB];
        cnt(a.x); cnt(a.y); cnt(a.z); cnt(a.w);
        cnt(b.x); cnt(b.y); cnt(b.z); cnt(b.w);
        cnt(c.x); cnt(c.y); cnt(c.z); cnt(c.w);
        cnt(e.x); cnt(e.y); cnt(e.z); cnt(e.w);
    }
    for (; j < len; j += TPB) {
        float4 v = d4[last - j];
        cnt(v.x); cnt(v.y); cnt(v.z); cnt(v.w);
    }
    int base = n4 * 4;
    int gtid = blockIdx.x * TPB + threadIdx.x;
    if (gtid < n - base) cnt(((const float*)d4)[base + gtid]);

    __shared__ unsigned s[5];
    if (threadIdx.x < 5) s[threadIdx.x] = 0;
    __syncthreads();
    #pragma unroll
    for (int k = 0; k < 5; k++)
        atomicAdd(&s[k], (unsigned)((acc >> (12 * k)) & 0xFFFull));
    __syncthreads();
    if (threadIdx.x < 5) atomicAdd(&g_hist[threadIdx.x], s[threadIdx.x]);
}

// ---- pass 3: slim transform, slice forward, __stcs stores ----------------
__global__ void __launch_bounds__(TPB) k_main(const float4* __restrict__ d4,
                                              const float* __restrict__ ctp,
                                              const float* __restrict__ stp,
                                              const float* __restrict__ params,
                                              float4* __restrict__ out,
                                              int n4, int n) {
    // sAB[j]  : index = A + B*x on segment j (x-space, ct folded in)
    // sTV[b]  : (thBase, thDelta, st*vlBase, st*vlDelta) -> one LDS.128
    __shared__ float2 sAB[4];
    __shared__ float4 sTV[5];
    __shared__ float  s_fsc, s_fbias;   // fi = x*fsc + fbias

    {
        float mn = FLTMAX, mx = -FLTMAX;
        for (int i = threadIdx.x; i < NBLK; i += TPB) {
            mn = fminf(mn, g_bmin[i]);
            mx = fmaxf(mx, g_bmax[i]);
        }
        #pragma unroll
        for (int o = 16; o; o >>= 1) {
            mn = fminf(mn, __shfl_xor_sync(0xffffffffu, mn, o));
            mx = fmaxf(mx, __shfl_xor_sync(0xffffffffu, mx, o));
        }
        __shared__ float smn[8], smx[8];
        int w = threadIdx.x >> 5;
        if ((threadIdx.x & 31) == 0) { smn[w] = mn; smx[w] = mx; }
        __syncthreads();

        if (threadIdx.x == 0) {
            #pragma unroll
            for (int k = 1; k < 8; k++) { mn = fminf(mn, smn[k]); mx = fmaxf(mx, smx[k]); }
            float ct = *ctp;
            float st = *stp;
            float a = ct * mn, b = ct * mx;
            float lo = fminf(a, b), hi = fmaxf(a, b);
            float dmin  = lo - 0.1f;
            float width = ((hi + 0.1f) - dmin) / 5.0f;
            float invw  = 1.0f / width;

            float counts[5];
            #pragma unroll
            for (int j = 0; j < 5; j++) counts[j] = fminf((float)g_hist[j], SATF);  // fp32 scatter-add saturation
            float sum = counts[0] + counts[1] + counts[2] + counts[3] + counts[4];
            float accum[5];
            float acn = 0.0f;
            #pragma unroll
            for (int j = 0; j < 5; j++) { acn += counts[j] / sum; accum[j] = acn * 5.0f; }
            float grid[5];
            #pragma unroll
            for (int i2 = 0; i2 < 5; i2++) {
                float e0 = dmin + width * (float)i2;
                float e1 = dmin + width * (float)(i2 + 1);
                grid[i2] = 0.5f * (e0 + e1);
            }
            #pragma unroll
            for (int j = 0; j < 4; j++) {
                float den = grid[j + 1] - grid[j];
                if (den == 0.0f) den = 1.0f;
                float slope = (accum[j + 1] - accum[j]) / den;
                // index = accum[j] + slope*(x*ct - grid[j]) = A + (slope*ct)*x
                sAB[j] = make_float2(accum[j] - slope * grid[j], slope * ct);
            }
            float frame[5];
            #pragma unroll
            for (int i2 = 0; i2 < 5; i2++) {
                float xq = (float)i2;
                int pos = 0;
                #pragma unroll
                for (int k = 0; k < 5; k++) pos += (accum[k] < xq);
                int idx = min(max(pos - 1, 0), 3);
                float den = accum[idx + 1] - accum[idx];
                if (den == 0.0f) den = 1.0f;
                frame[i2] = grid[idx] + (grid[idx + 1] - grid[idx]) / den * (xq - accum[idx]);
            }
            float tA[5], tV[5];
            #pragma unroll
            for (int i2 = 0; i2 < 5; i2++) {
                tA[i2] = frame[i2] + 0.001f * params[i2];
                tV[i2] = frame[i2] + 0.001f * params[5 + i2];
            }
            #pragma unroll
            for (int b2 = 0; b2 < 5; b2++) {
                int e2 = min(b2 + 1, 4);
                sTV[b2] = make_float4(tA[b2], tA[e2] - tA[b2],
                                      st * tV[b2], st * (tV[e2] - tV[b2]));
            }
            s_fsc   = ct * invw;            // fi = (x*ct - grid0)*invw
            s_fbias = -grid[0] * invw;
        }
        __syncthreads();
    }

    const float ct = __ldg(ctp), st = __ldg(stp);
    const float ctst = ct * st;
    const float fsc = s_fsc, fbias = s_fbias;

    auto f = [&](float x) -> float {
        float fi = fmaf(x, fsc, fbias);
        int idx  = min(max(__float2int_rd(fi), 0), 3);
        float2 ab = sAB[idx];
        float index = fmaf(ab.y, x, ab.x);
        float ic = fminf(fmaxf(index, 0.0f), 4.0f);   // matches ref b/e clip semantics
        float bf = floorf(ic);
        float p  = ic - bf;
        int b    = (int)bf;                            // 0..4
        float4 tv = sTV[b];
        float th = fmaf(p, tv.y, tv.x);
        float q  = fmaf(p, tv.w, tv.z);                // = st*velo
        float s, c;
        __sincosf(th, &s, &c);
        float v = x * ct;
        float u = fmaf(v, s, c);
        return fmaf(q, u, x * ctst);                   // st*v + q*(v*sin+cos)
    };

    int start, len;
    slice_bounds(n4, start, len);

    int j = threadIdx.x;
    for (; j + 3 * TPB < len; j += 4 * TPB) {
        float4 a = d4[start + j];
        float4 b = d4[start + j + TPB];
        float4 c = d4[start + j + 2 * TPB];
        float4 e = d4[start + j + 3 * TPB];
        float4 oa, ob, oc, oe;
        oa.x = f(a.x); oa.y = f(a.y); oa.z = f(a.z); oa.w = f(a.w);
        ob.x = f(b.x); ob.y = f(b.y); ob.z = f(b.z); ob.w = f(b.w);
        oc.x = f(c.x); oc.y = f(c.y); oc.z = f(c.z); oc.w = f(c.w);
        oe.x = f(e.x); oe.y = f(e.y); oe.z = f(e.z); oe.w = f(e.w);
        __stcs(&out[start + j], oa);
        __stcs(&out[start + j + TPB], ob);
        __stcs(&out[start + j + 2 * TPB], oc);
        __stcs(&out[start + j + 3 * TPB], oe);
    }
    for (; j < len; j += TPB) {
        float4 v = d4[start + j];
        float4 o;
        o.x = f(v.x); o.y = f(v.y); o.z = f(v.z); o.w = f(v.w);
        __stcs(&out[start + j], o);
    }
    int base = n4 * 4;
    int gtid = blockIdx.x * TPB + threadIdx.x;
    if (gtid < n - base) {
        float r = f(((const float*)d4)[base + gtid]);
        __stcs(&((float*)out)[base + gtid], r);
    }
}

extern "C" void kernel_launch(void* const* d_in, const int* in_sizes, int n_in,
                              void* d_out, int out_size) {
    const float* data   = (const float*)d_in[0];
    const float* params = (const float*)d_in[1];
    const float* ctp    = (const float*)d_in[2];
    const float* stp    = (const float*)d_in[3];
    float* out = (float*)d_out;
    int n  = in_sizes[0];
    int n4 = n / 4;

    k_minmax<<<NBLK, TPB>>>((const float4*)data, n4, n);
    k_hist<<<NBLK, TPB>>>((const float4*)data, ctp, n4, n);
    k_main<<<NBLK, TPB>>>((const float4*)data, ctp, stp, params, (float4*)out, n4, n);
}

// round 12
// speedup vs baseline: 1.2221x; 1.0244x over previous
#include <cuda_runtime.h>

// ---------------------------------------------------------------------------
// LNon_16621523436082 — 3 kernels:
//   k_minmax : GRID-STRIDE 4-wide min/max (proven 23.6us @73% spec)
//   k_hist   : sliced BACKWARD 5-bin histogram, packed 12-bit counters
//              (reads land on L2-resident lines; leaves slice starts hot)
//   k_main   : sliced FORWARD slim transform; __ldcs loads (last reader,
//              evict-first) + __stcs stores (don't thrash L2)
// ---------------------------------------------------------------------------

#define NBLK 2048
#define TPB  256
#define SATF 16777216.0f
#define FLTMAX 3.4028235e38f

__device__ float    g_bmin[NBLK];
__device__ float    g_bmax[NBLK];
__device__ unsigned g_hist[8];

__device__ __forceinline__ void slice_bounds(int n4, int& start, int& len) {
    int base = n4 / NBLK, rem = n4 % NBLK;
    start = blockIdx.x * base + min((int)blockIdx.x, rem);
    len   = base + (blockIdx.x < rem ? 1 : 0);
}

// ---- pass 1: per-block min/max, grid-stride ------------------------------
__global__ void __launch_bounds__(TPB) k_minmax(const float4* __restrict__ d4, int n4, int n) {
    if (blockIdx.x == 0 && threadIdx.x < 8) g_hist[threadIdx.x] = 0u;  // replay-safe reset

    float mn = FLTMAX, mx = -FLTMAX;
    const int stride = gridDim.x * blockDim.x;
    const int gtid = blockIdx.x * blockDim.x + threadIdx.x;

    auto red = [&](float4 v) {
        mn = fminf(mn, fminf(fminf(v.x, v.y), fminf(v.z, v.w)));
        mx = fmaxf(mx, fmaxf(fmaxf(v.x, v.y), fmaxf(v.z, v.w)));
    };

    int i = gtid;
    for (; i + 3 * stride < n4; i += 4 * stride) {
        float4 a = d4[i];
        float4 b = d4[i + stride];
        float4 c = d4[i + 2 * stride];
        float4 e = d4[i + 3 * stride];
        red(a); red(b); red(c); red(e);
    }
    for (; i < n4; i += stride) red(d4[i]);

    int base = n4 * 4;
    if (gtid < n - base) {
        float v = ((const float*)d4)[base + gtid];
        mn = fminf(mn, v); mx = fmaxf(mx, v);
    }
    #pragma unroll
    for (int o = 16; o; o >>= 1) {
        mn = fminf(mn, __shfl_xor_sync(0xffffffffu, mn, o));
        mx = fmaxf(mx, __shfl_xor_sync(0xffffffffu, mx, o));
    }
    __shared__ float smn[8], smx[8];
    int w = threadIdx.x >> 5;
    if ((threadIdx.x & 31) == 0) { smn[w] = mn; smx[w] = mx; }
    __syncthreads();
    if (threadIdx.x < 8) {
        mn = smn[threadIdx.x]; mx = smx[threadIdx.x];
        #pragma unroll
        for (int o = 4; o; o >>= 1) {
            mn = fminf(mn, __shfl_xor_sync(0xffu, mn, o));
            mx = fmaxf(mx, __shfl_xor_sync(0xffu, mx, o));
        }
        if (threadIdx.x == 0) { g_bmin[blockIdx.x] = mn; g_bmax[blockIdx.x] = mx; }
    }
}

// ---- pass 2: per-block prep + 5-bin histogram, slice backward ------------
__global__ void __launch_bounds__(TPB) k_hist(const float4* __restrict__ d4,
                                              const float* __restrict__ ctp,
                                              int n4, int n) {
    __shared__ float s_scale, s_bias;   // bin = floor(x*scale + bias)
    {
        float mn = FLTMAX, mx = -FLTMAX;
        for (int i = threadIdx.x; i < NBLK; i += TPB) {
            mn = fminf(mn, g_bmin[i]);
            mx = fmaxf(mx, g_bmax[i]);
        }
        #pragma unroll
        for (int o = 16; o; o >>= 1) {
            mn = fminf(mn, __shfl_xor_sync(0xffffffffu, mn, o));
            mx = fmaxf(mx, __shfl_xor_sync(0xffffffffu, mx, o));
        }
        __shared__ float smn[8], smx[8];
        int w = threadIdx.x >> 5;
        if ((threadIdx.x & 31) == 0) { smn[w] = mn; smx[w] = mx; }
        __syncthreads();
        if (threadIdx.x == 0) {
            #pragma unroll
            for (int k = 1; k < 8; k++) { mn = fminf(mn, smn[k]); mx = fmaxf(mx, smx[k]); }
            float ct = *ctp;
            float a = ct * mn, b = ct * mx;
            float lo = fminf(a, b), hi = fmaxf(a, b);
            float dmin  = lo - 0.1f;
            float width = ((hi + 0.1f) - dmin) / 5.0f;
            float invw  = 1.0f / width;
            s_scale = ct * invw;        // (x*ct - dmin)*invw = x*scale + bias
            s_bias  = -dmin * invw;
        }
        __syncthreads();
    }
    const float scale = s_scale, bias = s_bias;

    // packed counters: 5 fields x 12 bits (per-thread <= ~70 elems, fits)
    unsigned long long acc = 0ull;
    auto cnt = [&](float x) {
        int b = __float2int_rd(fmaf(x, scale, bias));
        b = min(max(b, 0), 4);
        acc += 1ull << (b * 12);
    };

    int start, len;
    slice_bounds(n4, start, len);
    int last = start + len - 1;

    int j = threadIdx.x;
    for (; j + 3 * TPB < len; j += 4 * TPB) {
        float4 a = d4[last - j];
        float4 b = d4[last - j - TPB];
        float4 c = d4[last - j - 2 * TPB];
        float4 e = d4[last - j - 3 * TPB];
        cnt(a.x); cnt(a.y); cnt(a.z); cnt(a.w);
        cnt(b.x); cnt(b.y); cnt(b.z); cnt(b.w);
        cnt(c.x); cnt(c.y); cnt(c.z); cnt(c.w);
        cnt(e.x); cnt(e.y); cnt(e.z); cnt(e.w);
    }
    for (; j < len; j += TPB) {
        float4 v = d4[last - j];
        cnt(v.x); cnt(v.y); cnt(v.z); cnt(v.w);
    }
    int base = n4 * 4;
    int gtid = blockIdx.x * TPB + threadIdx.x;
    if (gtid < n - base) cnt(((const float*)d4)[base + gtid]);

    __shared__ unsigned s[5];
    if (threadIdx.x < 5) s[threadIdx.x] = 0;
    __syncthreads();
    #pragma unroll
    for (int k = 0; k < 5; k++)
        atomicAdd(&s[k], (unsigned)((acc >> (12 * k)) & 0xFFFull));
    __syncthreads();
    if (threadIdx.x < 5) atomicAdd(&g_hist[threadIdx.x], s[threadIdx.x]);
}

// ---- pass 3: slim transform, slice forward, __ldcs/__stcs ----------------
__global__ void __launch_bounds__(TPB) k_main(const float4* __restrict__ d4,
                                              const float* __restrict__ ctp,
                                              const float* __restrict__ stp,
                                              const float* __restrict__ params,
                                              float4* __restrict__ out,
                                              int n4, int n) {
    // sAB[j]  : index = A + B*x on segment j (x-space, ct folded in)
    // sTV[b]  : (thBase, thDelta, st*vlBase, st*vlDelta) -> one LDS.128
    __shared__ float2 sAB[4];
    __shared__ float4 sTV[5];
    __shared__ float  s_fsc, s_fbias;   // fi = x*fsc + fbias

    {
        float mn = FLTMAX, mx = -FLTMAX;
        for (int i = threadIdx.x; i < NBLK; i += TPB) {
            mn = fminf(mn, g_bmin[i]);
            mx = fmaxf(mx, g_bmax[i]);
        }
        #pragma unroll
        for (int o = 16; o; o >>= 1) {
            mn = fminf(mn, __shfl_xor_sync(0xffffffffu, mn, o));
            mx = fmaxf(mx, __shfl_xor_sync(0xffffffffu, mx, o));
        }
        __shared__ float smn[8], smx[8];
        int w = threadIdx.x >> 5;
        if ((threadIdx.x & 31) == 0) { smn[w] = mn; smx[w] = mx; }
        __syncthreads();

        if (threadIdx.x == 0) {
            #pragma unroll
            for (int k = 1; k < 8; k++) { mn = fminf(mn, smn[k]); mx = fmaxf(mx, smx[k]); }
            float ct = *ctp;
            float st = *stp;
            float a = ct * mn, b = ct * mx;
            float lo = fminf(a, b), hi = fmaxf(a, b);
            float dmin  = lo - 0.1f;
            float width = ((hi + 0.1f) - dmin) / 5.0f;
            float invw  = 1.0f / width;

            float counts[5];
            #pragma unroll
            for (int j = 0; j < 5; j++) counts[j] = fminf((float)g_hist[j], SATF);  // fp32 scatter-add saturation
            float sum = counts[0] + counts[1] + counts[2] + counts[3] + counts[4];
            float accum[5];
            float acn = 0.0f;
            #pragma unroll
            for (int j = 0; j < 5; j++) { acn += counts[j] / sum; accum[j] = acn * 5.0f; }
            float grid[5];
            #pragma unroll
            for (int i2 = 0; i2 < 5; i2++) {
                float e0 = dmin + width * (float)i2;
                float e1 = dmin + width * (float)(i2 + 1);
                grid[i2] = 0.5f * (e0 + e1);
            }
            #pragma unroll
            for (int j = 0; j < 4; j++) {
                float den = grid[j + 1] - grid[j];
                if (den == 0.0f) den = 1.0f;
                float slope = (accum[j + 1] - accum[j]) / den;
                // index = accum[j] + slope*(x*ct - grid[j]) = A + (slope*ct)*x
                sAB[j] = make_float2(accum[j] - slope * grid[j], slope * ct);
            }
            float frame[5];
            #pragma unroll
            for (int i2 = 0; i2 < 5; i2++) {
                float xq = (float)i2;
                int pos = 0;
                #pragma unroll
                for (int k = 0; k < 5; k++) pos += (accum[k] < xq);
                int idx = min(max(pos - 1, 0), 3);
                float den = accum[idx + 1] - accum[idx];
                if (den == 0.0f) den = 1.0f;
                frame[i2] = grid[idx] + (grid[idx + 1] - grid[idx]) / den * (xq - accum[idx]);
            }
            float tA[5], tV[5];
            #pragma unroll
            for (int i2 = 0; i2 < 5; i2++) {
                tA[i2] = frame[i2] + 0.001f * params[i2];
                tV[i2] = frame[i2] + 0.001f * params[5 + i2];
            }
            #pragma unroll
            for (int b2 = 0; b2 < 5; b2++) {
                int e2 = min(b2 + 1, 4);
                sTV[b2] = make_float4(tA[b2], tA[e2] - tA[b2],
                                      st * tV[b2], st * (tV[e2] - tV[b2]));
            }
            s_fsc   = ct * invw;            // fi = (x*ct - grid0)*invw
            s_fbias = -grid[0] * invw;
        }
        __syncthreads();
    }

    const float ct = __ldg(ctp), st = __ldg(stp);
    const float ctst = ct * st;
    const float fsc = s_fsc, fbias = s_fbias;

    auto f = [&](float x) -> float {
        float fi = fmaf(x, fsc, fbias);
        int idx  = min(max(__float2int_rd(fi), 0), 3);
        float2 ab = sAB[idx];
        float index = fmaf(ab.y, x, ab.x);
        float ic = fminf(fmaxf(index, 0.0f), 4.0f);   // matches ref b/e clip semantics
        float bf = floorf(ic);
        float p  = ic - bf;
        int b    = (int)bf;                            // 0..4
        float4 tv = sTV[b];
        float th = fmaf(p, tv.y, tv.x);
        float q  = fmaf(p, tv.w, tv.z);                // = st*velo
        float s, c;
        __sincosf(th, &s, &c);
        float v = x * ct;
        float u = fmaf(v, s, c);
        return fmaf(q, u, x * ctst);                   // st*v + q*(v*sin+cos)
    };

    int start, len;
    slice_bounds(n4, start, len);

    int j = threadIdx.x;
    for (; j + 3 * TPB < len; j += 4 * TPB) {
        float4 a = __ldcs(&d4[start + j]);
        float4 b = __ldcs(&d4[start + j + TPB]);
        float4 c = __ldcs(&d4[start + j + 2 * TPB]);
        float4 e = __ldcs(&d4[start + j + 3 * TPB]);
        float4 oa, ob, oc, oe;
        oa.x = f(a.x); oa.y = f(a.y); oa.z = f(a.z); oa.w = f(a.w);
        ob.x = f(b.x); ob.y = f(b.y); ob.z = f(b.z); ob.w = f(b.w);
        oc.x = f(c.x); oc.y = f(c.y); oc.z = f(c.z); oc.w = f(c.w);
        oe.x = f(e.x); oe.y = f(e.y); oe.z = f(e.z); oe.w = f(e.w);
        __stcs(&out[start + j], oa);
        __stcs(&out[start + j + TPB], ob);
        __stcs(&out[start + j + 2 * TPB], oc);
        __stcs(&out[start + j + 3 * TPB], oe);
    }
    for (; j < len; j += TPB) {
        float4 v = __ldcs(&d4[start + j]);
        float4 o;
        o.x = f(v.x); o.y = f(v.y); o.z = f(v.z); o.w = f(v.w);
        __stcs(&out[start + j], o);
    }
    int base = n4 * 4;
    int gtid = blockIdx.x * TPB + threadIdx.x;
    if (gtid < n - base) {
        float r = f(__ldcs(&((const float*)d4)[base + gtid]));
        __stcs(&((float*)out)[base + gtid], r);
    }
}

extern "C" void kernel_launch(void* const* d_in, const int* in_sizes, int n_in,
                              void* d_out, int out_size) {
    const float* data   = (const float*)d_in[0];
    const float* params = (const float*)d_in[1];
    const float* ctp    = (const float*)d_in[2];
    const float* stp    = (const float*)d_in[3];
    float* out = (float*)d_out;
    int n  = in_sizes[0];
    int n4 = n / 4;

    k_minmax<<<NBLK, TPB>>>((const float4*)data, n4, n);
    k_hist<<<NBLK, TPB>>>((const float4*)data, ctp, n4, n);
    k_main<<<NBLK, TPB>>>((const float4*)data, ctp, stp, params, (float4*)out, n4, n);
}